// round 15
// baseline (speedup 1.0000x reference)
#include <cuda_runtime.h>
#include <cstdint>

// scGNN: 2-layer GCN on GB300 — CSR-gather formulation (no feature atomics).
//   out = A·relu(A·(x@W1) + b1) @ W2 + b2, A = sym-norm adjacency w/ self-loops.
// Layer-2 aggregation commuted past W2 -> both aggregations 32-wide.
// CSR by dst built once (count -> scan -> fill). Aggregation = per-node gather:
// broadcast 8B edge record + 128B row gather per edge, ONE row store per node.
// relu+bias and self-loop terms fused into gather epilogues.
// R15: k_scan2 parallelized (was a 1-thread 8us latency chain); off/cnt packed.

#define NN   100000
#define EE   1200000
#define FIN  64
#define FMID 32
#define SCAN_B 1024

static __device__ int   g_is64;
static __device__ int   g_cnt [NN];             // in-degree (excl self)
static __device__ int   g_off [NN];             // CSR exclusive offsets
static __device__ int   g_cur [NN];             // fill cursors
static __device__ int   g_bsum[128];            // scan block sums
static __device__ int   g_bpre[128];            // scan block prefixes
static __device__ __align__(16) int2  g_oc [NN];        // packed {off, cnt}
static __device__ __align__(16) float g_deg[NN];        // cnt+1 (incl self)
static __device__ __align__(16) int2  g_elist[EE];      // {src*32, norm bits}
static __device__ __align__(16) float g_h1[NN * FMID];  // x @ W1
static __device__ __align__(16) float g_r [NN * FMID];  // relu(A·h1 + b1)
static __device__ __align__(16) float g_a2[NN * FMID];  // A·r

// ---------------------------------------------------------------------------
__device__ __forceinline__ int get_idx(const void* ei, int pos) {
    int v = g_is64 ? (int)((const long long*)ei)[pos]
                   : ((const int*)ei)[pos];
    return min(max(v, 0), NN - 1);
}

// cnt := 0 ; block 0 detects edge-index dtype.
__global__ void k_count0(const int* __restrict__ ei, int n) {
    int i = blockIdx.x * blockDim.x + threadIdx.x;
    if (i < n) g_cnt[i] = 0;
    if (blockIdx.x == 0) {
        __shared__ int nz;
        if (threadIdx.x == 0) nz = 0;
        __syncthreads();
        for (int k = threadIdx.x; k < 2048; k += blockDim.x)
            if (ei[2 * k + 1] != 0) nz = 1;
        __syncthreads();
        if (threadIdx.x == 0) g_is64 = (nz == 0) ? 1 : 0;
    }
}

__global__ void k_deg_count(const void* __restrict__ ei, int E) {
    int e = blockIdx.x * blockDim.x + threadIdx.x;
    if (e < E) atomicAdd(&g_cnt[get_idx(ei, E + e)], 1);
}

// Per-block exclusive scan (1024 threads); block totals to g_bsum.
__global__ void __launch_bounds__(SCAN_B) k_scan1(int n) {
    int i = blockIdx.x * SCAN_B + threadIdx.x;
    int v = (i < n) ? g_cnt[i] : 0;
    int lane = threadIdx.x & 31, w = threadIdx.x >> 5;
    int s = v;
#pragma unroll
    for (int o = 1; o < 32; o <<= 1) {
        int t = __shfl_up_sync(0xffffffffu, s, o);
        if (lane >= o) s += t;
    }
    __shared__ int wsum[32];
    if (lane == 31) wsum[w] = s;
    __syncthreads();
    if (w == 0) {
        int t = wsum[lane];
#pragma unroll
        for (int o = 1; o < 32; o <<= 1) {
            int u = __shfl_up_sync(0xffffffffu, t, o);
            if (lane >= o) t += u;
        }
        wsum[lane] = t;
    }
    __syncthreads();
    int inc = s + (w > 0 ? wsum[w - 1] : 0);
    if (i < n) g_off[i] = inc - v;                   // exclusive within block
    if (threadIdx.x == SCAN_B - 1) g_bsum[blockIdx.x] = inc;
}

// Parallel scan of <=128 block sums: one 128-thread block, shuffle scan.
__global__ void __launch_bounds__(128) k_scan2(int nb) {
    int tid  = threadIdx.x;
    int lane = tid & 31, w = tid >> 5;
    int v = (tid < nb) ? g_bsum[tid] : 0;
    int s = v;
#pragma unroll
    for (int o = 1; o < 32; o <<= 1) {
        int t = __shfl_up_sync(0xffffffffu, s, o);
        if (lane >= o) s += t;
    }
    __shared__ int wsum[4];
    if (lane == 31) wsum[w] = s;
    __syncthreads();
    __shared__ int wpre[4];
    if (tid == 0) {
        int run = 0;
#pragma unroll
        for (int b = 0; b < 4; b++) { wpre[b] = run; run += wsum[b]; }
    }
    __syncthreads();
    if (tid < nb) g_bpre[tid] = s - v + wpre[w];     // exclusive prefix
}

// Finalize packed {off,cnt}, cursors, and float degree (incl self-loop).
__global__ void k_scan3(int n) {
    int i = blockIdx.x * blockDim.x + threadIdx.x;
    if (i >= n) return;
    int off = g_off[i] + g_bpre[i >> 10];
    int cnt = g_cnt[i];
    g_oc[i]  = make_int2(off, cnt);
    g_cur[i] = off;
    g_deg[i] = (float)(cnt + 1);
}

// Fill CSR edge list: record = {src*32, norm}, norm = rsqrt(deg_s*deg_d).
__global__ void k_fill(const void* __restrict__ ei, int E) {
    int e = blockIdx.x * blockDim.x + threadIdx.x;
    if (e >= E) return;
    int s = get_idx(ei, e);
    int d = get_idx(ei, E + e);
    float nm = rsqrtf(g_deg[s] * g_deg[d]);
    int pos = atomicAdd(&g_cur[d], 1);
    g_elist[pos] = make_int2(s * FMID, __float_as_int(nm));
}

// ---------------------------------------------------------------------------
// GEMM1: h1 = x@W1. Thread: 4 nodes x 8 cols; weight-LDS amortized 4x.
__global__ void __launch_bounds__(256) k_gemm1(const float* __restrict__ x,
                                               const float* __restrict__ W1,
                                               int n) {
    __shared__ float ws[FIN * FMID];    // 8 KB
    int tid = threadIdx.x;
    for (int i = tid; i < FIN * FMID; i += 256) ws[i] = W1[i];
    __syncthreads();

    int warp = tid >> 5, lane = tid & 31;
    int n0 = blockIdx.x * 256 + warp * 32 + (lane >> 2) * 4;  // 4 nodes
    int c0 = (lane & 3) * 8;

    float acc[4][8];
#pragma unroll
    for (int i = 0; i < 4; i++)
#pragma unroll
        for (int j = 0; j < 8; j++) acc[i][j] = 0.0f;

#pragma unroll 4
    for (int k4 = 0; k4 < 16; k4++) {
        float4 xv[4];
#pragma unroll
        for (int i = 0; i < 4; i++)
            xv[i] = (n0 + i < n)
                ? __ldg(reinterpret_cast<const float4*>(&x[(n0 + i) * FIN + k4 * 4]))
                : make_float4(0.f, 0.f, 0.f, 0.f);
#pragma unroll
        for (int u = 0; u < 4; u++) {
            int k = k4 * 4 + u;
            float4 wa = *reinterpret_cast<const float4*>(&ws[k * FMID + c0]);
            float4 wb = *reinterpret_cast<const float4*>(&ws[k * FMID + c0 + 4]);
            float wr[8] = {wa.x, wa.y, wa.z, wa.w, wb.x, wb.y, wb.z, wb.w};
            float xu[4] = {
                u == 0 ? xv[0].x : u == 1 ? xv[0].y : u == 2 ? xv[0].z : xv[0].w,
                u == 0 ? xv[1].x : u == 1 ? xv[1].y : u == 2 ? xv[1].z : xv[1].w,
                u == 0 ? xv[2].x : u == 1 ? xv[2].y : u == 2 ? xv[2].z : xv[2].w,
                u == 0 ? xv[3].x : u == 1 ? xv[3].y : u == 2 ? xv[3].z : xv[3].w};
#pragma unroll
            for (int i = 0; i < 4; i++)
#pragma unroll
                for (int j = 0; j < 8; j++) acc[i][j] += xu[i] * wr[j];
        }
    }

#pragma unroll
    for (int i = 0; i < 4; i++) {
        int node = n0 + i;
        if (node >= n) break;
        *reinterpret_cast<float4*>(&g_h1[node * FMID + c0]) =
            make_float4(acc[i][0], acc[i][1], acc[i][2], acc[i][3]);
        *reinterpret_cast<float4*>(&g_h1[node * FMID + c0 + 4]) =
            make_float4(acc[i][4], acc[i][5], acc[i][6], acc[i][7]);
    }
}

// CSR gather aggregation, 8 threads/node (thread = 4 cols of the 32-wide row).
// which=0: src=h1, epilogue r = relu(agg + self + b1)   -> g_r
// which=1: src=r,  epilogue a2 = agg + self             -> g_a2
__global__ void __launch_bounds__(256) k_gather(int which,
                                                const float* __restrict__ b1,
                                                int n) {
    int t = blockIdx.x * blockDim.x + threadIdx.x;
    int node = t >> 3;
    if (node >= n) return;
    int q = (t & 7) * 4;
    const float* __restrict__ src = which ? g_r : g_h1;

    int2 oc = g_oc[node];                       // packed {off, cnt}, broadcast
    int off = oc.x, end = oc.x + oc.y;
    float4 acc = make_float4(0.f, 0.f, 0.f, 0.f);
    for (int p = off; p < end; p++) {
        int2  rec = g_elist[p];                 // 8 lanes broadcast
        float nm  = __int_as_float(rec.y);
        float4 v = *reinterpret_cast<const float4*>(&src[rec.x + q]);
        acc.x += v.x * nm; acc.y += v.y * nm;
        acc.z += v.z * nm; acc.w += v.w * nm;
    }
    float w = 1.0f / g_deg[node];               // dinv^2 (self-loop norm)
    float4 sv = *reinterpret_cast<const float4*>(&src[node * FMID + q]);
    acc.x += w * sv.x; acc.y += w * sv.y;
    acc.z += w * sv.z; acc.w += w * sv.w;

    if (which == 0) {
        float4 bb = *reinterpret_cast<const float4*>(&b1[q]);
        *reinterpret_cast<float4*>(&g_r[node * FMID + q]) =
            make_float4(fmaxf(acc.x + bb.x, 0.f), fmaxf(acc.y + bb.y, 0.f),
                        fmaxf(acc.z + bb.z, 0.f), fmaxf(acc.w + bb.w, 0.f));
    } else {
        *reinterpret_cast<float4*>(&g_a2[node * FMID + q]) = acc;
    }
}

// GEMM2: out = a2@W2 + b2. Block = 256 thr, 128 nodes (25 KB smem).
__global__ void __launch_bounds__(256) k_gemm2(const float* __restrict__ W2,
                                               const float* __restrict__ b2,
                                               float* __restrict__ out, int n) {
    __shared__ float as_[32 * 132];  // a2 transposed [k][node], pad 4
    __shared__ float ws[32 * 64];
    int tid  = threadIdx.x;
    int base = blockIdx.x * 128;

    for (int i = tid; i < 32 * 64; i += 256) ws[i] = W2[i];
    for (int i = tid; i < 128 * 32; i += 256) {
        int node = i >> 5, k = i & 31;
        as_[k * 132 + node] =
            (base + node < n) ? g_a2[(base + node) * FMID + k] : 0.0f;
    }
    __syncthreads();

    int warp = tid >> 5, lane = tid & 31;
    int n0 = warp * 16 + (lane >> 3) * 4;
    int c0 = (lane & 7) * 8;

    float acc[4][8];
#pragma unroll
    for (int i = 0; i < 4; i++)
#pragma unroll
        for (int j = 0; j < 8; j++) acc[i][j] = 0.0f;

#pragma unroll 8
    for (int k = 0; k < 32; k++) {
        float4 xv = *reinterpret_cast<const float4*>(&as_[k * 132 + n0]);
        float4 wa = *reinterpret_cast<const float4*>(&ws[k * 64 + c0]);
        float4 wb = *reinterpret_cast<const float4*>(&ws[k * 64 + c0 + 4]);
        float xr[4] = {xv.x, xv.y, xv.z, xv.w};
        float wr[8] = {wa.x, wa.y, wa.z, wa.w, wb.x, wb.y, wb.z, wb.w};
#pragma unroll
        for (int i = 0; i < 4; i++)
#pragma unroll
            for (int j = 0; j < 8; j++) acc[i][j] += xr[i] * wr[j];
    }

    float4 ba  = *reinterpret_cast<const float4*>(&b2[c0]);
    float4 bbv = *reinterpret_cast<const float4*>(&b2[c0 + 4]);
#pragma unroll
    for (int i = 0; i < 4; i++) {
        int node = base + n0 + i;
        if (node >= n) break;
        *reinterpret_cast<float4*>(&out[node * FIN + c0]) =
            make_float4(acc[i][0] + ba.x, acc[i][1] + ba.y,
                        acc[i][2] + ba.z, acc[i][3] + ba.w);
        *reinterpret_cast<float4*>(&out[node * FIN + c0 + 4]) =
            make_float4(acc[i][4] + bbv.x, acc[i][5] + bbv.y,
                        acc[i][6] + bbv.z, acc[i][7] + bbv.w);
    }
}

// ---------------------------------------------------------------------------
extern "C" void kernel_launch(void* const* d_in, const int* in_sizes, int n_in,
                              void* d_out, int out_size) {
    const float* x  = (const float*)d_in[0];
    const void*  ei = d_in[1];                 // edge_index [2,E], int32
    const float* W1 = (const float*)d_in[2];
    const float* b1 = (const float*)d_in[3];
    const float* W2 = (const float*)d_in[4];
    const float* b2 = (const float*)d_in[5];
    float*       out = (float*)d_out;

    const int N = in_sizes[0] / FIN;   // 100000
    const int E = in_sizes[1] / 2;     // 1200000
    const int NB = (N + SCAN_B - 1) / SCAN_B;   // 98 scan blocks

    const int T = 256;
    k_count0   <<<(N + T - 1) / T, T>>>((const int*)ei, N);
    k_deg_count<<<(E + T - 1) / T, T>>>(ei, E);
    k_scan1    <<<NB, SCAN_B>>>(N);
    k_scan2    <<<1, 128>>>(NB);
    k_scan3    <<<(N + T - 1) / T, T>>>(N);
    k_fill     <<<(E + T - 1) / T, T>>>(ei, E);

    k_gemm1 <<<(N + 255) / 256, 256>>>(x, W1, N);
    k_gather<<<(N * 8 + T - 1) / T, T>>>(0, b1, N);
    k_gather<<<(N * 8 + T - 1) / T, T>>>(1, b1, N);
    k_gemm2 <<<(N + 127) / 128, 256>>>(W2, b2, out, N);
}

// round 16
// speedup vs baseline: 1.4450x; 1.4450x over previous
#include <cuda_runtime.h>
#include <cstdint>

// scGNN: 2-layer GCN on GB300 — CSR-gather formulation (no feature atomics).
//   out = A·relu(A·(x@W1) + b1) @ W2 + b2, A = sym-norm adjacency w/ self-loops.
// Layer-2 aggregation commuted past W2 -> both aggregations 32-wide.
// CSR by dst built once (count -> scan -> fill). Aggregation = per-node gather:
// broadcast 8B edge record + 128B row gather per edge, ONE row store per node.
// relu+bias and self-loop terms fused into gather epilogues.
// R16 = R14 exactly (the 133us trunk) + parallel k_scan2 only (A/B vs R15:
// the off/cnt packing is REVERTED to isolate R15's unexplained regression).

#define NN   100000
#define EE   1200000
#define FIN  64
#define FMID 32
#define SCAN_B 1024

static __device__ int   g_is64;
static __device__ int   g_cnt [NN];             // in-degree (excl self)
static __device__ int   g_off [NN];             // CSR exclusive offsets
static __device__ int   g_cur [NN];             // fill cursors
static __device__ int   g_bsum[128];            // scan block sums
static __device__ int   g_bpre[128];            // scan block prefixes
static __device__ __align__(16) float g_deg[NN];        // cnt+1 (incl self)
static __device__ __align__(16) int2  g_elist[EE];      // {src*32, norm bits}
static __device__ __align__(16) float g_h1[NN * FMID];  // x @ W1
static __device__ __align__(16) float g_r [NN * FMID];  // relu(A·h1 + b1)
static __device__ __align__(16) float g_a2[NN * FMID];  // A·r

// ---------------------------------------------------------------------------
__device__ __forceinline__ int get_idx(const void* ei, int pos) {
    int v = g_is64 ? (int)((const long long*)ei)[pos]
                   : ((const int*)ei)[pos];
    return min(max(v, 0), NN - 1);
}

// cnt := 0 ; block 0 detects edge-index dtype.
__global__ void k_count0(const int* __restrict__ ei, int n) {
    int i = blockIdx.x * blockDim.x + threadIdx.x;
    if (i < n) g_cnt[i] = 0;
    if (blockIdx.x == 0) {
        __shared__ int nz;
        if (threadIdx.x == 0) nz = 0;
        __syncthreads();
        for (int k = threadIdx.x; k < 2048; k += blockDim.x)
            if (ei[2 * k + 1] != 0) nz = 1;
        __syncthreads();
        if (threadIdx.x == 0) g_is64 = (nz == 0) ? 1 : 0;
    }
}

__global__ void k_deg_count(const void* __restrict__ ei, int E) {
    int e = blockIdx.x * blockDim.x + threadIdx.x;
    if (e < E) atomicAdd(&g_cnt[get_idx(ei, E + e)], 1);
}

// Per-block exclusive scan (1024 threads); block totals to g_bsum.
__global__ void __launch_bounds__(SCAN_B) k_scan1(int n) {
    int i = blockIdx.x * SCAN_B + threadIdx.x;
    int v = (i < n) ? g_cnt[i] : 0;
    int lane = threadIdx.x & 31, w = threadIdx.x >> 5;
    int s = v;
#pragma unroll
    for (int o = 1; o < 32; o <<= 1) {
        int t = __shfl_up_sync(0xffffffffu, s, o);
        if (lane >= o) s += t;
    }
    __shared__ int wsum[32];
    if (lane == 31) wsum[w] = s;
    __syncthreads();
    if (w == 0) {
        int t = wsum[lane];
#pragma unroll
        for (int o = 1; o < 32; o <<= 1) {
            int u = __shfl_up_sync(0xffffffffu, t, o);
            if (lane >= o) t += u;
        }
        wsum[lane] = t;
    }
    __syncthreads();
    int inc = s + (w > 0 ? wsum[w - 1] : 0);
    if (i < n) g_off[i] = inc - v;                   // exclusive within block
    if (threadIdx.x == SCAN_B - 1) g_bsum[blockIdx.x] = inc;
}

// Parallel scan of <=128 block sums: one 128-thread block, shuffle scan.
__global__ void __launch_bounds__(128) k_scan2(int nb) {
    int tid  = threadIdx.x;
    int lane = tid & 31, w = tid >> 5;
    int v = (tid < nb) ? g_bsum[tid] : 0;
    int s = v;
#pragma unroll
    for (int o = 1; o < 32; o <<= 1) {
        int t = __shfl_up_sync(0xffffffffu, s, o);
        if (lane >= o) s += t;
    }
    __shared__ int wsum[4];
    if (lane == 31) wsum[w] = s;
    __syncthreads();
    __shared__ int wpre[4];
    if (tid == 0) {
        int run = 0;
#pragma unroll
        for (int b = 0; b < 4; b++) { wpre[b] = run; run += wsum[b]; }
    }
    __syncthreads();
    if (tid < nb) g_bpre[tid] = s - v + wpre[w];     // exclusive prefix
}

// Finalize offsets, cursors, and float degree (incl self-loop).
__global__ void k_scan3(int n) {
    int i = blockIdx.x * blockDim.x + threadIdx.x;
    if (i >= n) return;
    int off = g_off[i] + g_bpre[i >> 10];
    g_off[i] = off;
    g_cur[i] = off;
    g_deg[i] = (float)(g_cnt[i] + 1);
}

// Fill CSR edge list: record = {src*32, norm}, norm = rsqrt(deg_s*deg_d).
__global__ void k_fill(const void* __restrict__ ei, int E) {
    int e = blockIdx.x * blockDim.x + threadIdx.x;
    if (e >= E) return;
    int s = get_idx(ei, e);
    int d = get_idx(ei, E + e);
    float nm = rsqrtf(g_deg[s] * g_deg[d]);
    int pos = atomicAdd(&g_cur[d], 1);
    g_elist[pos] = make_int2(s * FMID, __float_as_int(nm));
}

// ---------------------------------------------------------------------------
// GEMM1: h1 = x@W1. Thread: 4 nodes x 8 cols; weight-LDS amortized 4x.
__global__ void __launch_bounds__(256) k_gemm1(const float* __restrict__ x,
                                               const float* __restrict__ W1,
                                               int n) {
    __shared__ float ws[FIN * FMID];    // 8 KB
    int tid = threadIdx.x;
    for (int i = tid; i < FIN * FMID; i += 256) ws[i] = W1[i];
    __syncthreads();

    int warp = tid >> 5, lane = tid & 31;
    int n0 = blockIdx.x * 256 + warp * 32 + (lane >> 2) * 4;  // 4 nodes
    int c0 = (lane & 3) * 8;

    float acc[4][8];
#pragma unroll
    for (int i = 0; i < 4; i++)
#pragma unroll
        for (int j = 0; j < 8; j++) acc[i][j] = 0.0f;

#pragma unroll 4
    for (int k4 = 0; k4 < 16; k4++) {
        float4 xv[4];
#pragma unroll
        for (int i = 0; i < 4; i++)
            xv[i] = (n0 + i < n)
                ? __ldg(reinterpret_cast<const float4*>(&x[(n0 + i) * FIN + k4 * 4]))
                : make_float4(0.f, 0.f, 0.f, 0.f);
#pragma unroll
        for (int u = 0; u < 4; u++) {
            int k = k4 * 4 + u;
            float4 wa = *reinterpret_cast<const float4*>(&ws[k * FMID + c0]);
            float4 wb = *reinterpret_cast<const float4*>(&ws[k * FMID + c0 + 4]);
            float wr[8] = {wa.x, wa.y, wa.z, wa.w, wb.x, wb.y, wb.z, wb.w};
            float xu[4] = {
                u == 0 ? xv[0].x : u == 1 ? xv[0].y : u == 2 ? xv[0].z : xv[0].w,
                u == 0 ? xv[1].x : u == 1 ? xv[1].y : u == 2 ? xv[1].z : xv[1].w,
                u == 0 ? xv[2].x : u == 1 ? xv[2].y : u == 2 ? xv[2].z : xv[2].w,
                u == 0 ? xv[3].x : u == 1 ? xv[3].y : u == 2 ? xv[3].z : xv[3].w};
#pragma unroll
            for (int i = 0; i < 4; i++)
#pragma unroll
                for (int j = 0; j < 8; j++) acc[i][j] += xu[i] * wr[j];
        }
    }

#pragma unroll
    for (int i = 0; i < 4; i++) {
        int node = n0 + i;
        if (node >= n) break;
        *reinterpret_cast<float4*>(&g_h1[node * FMID + c0]) =
            make_float4(acc[i][0], acc[i][1], acc[i][2], acc[i][3]);
        *reinterpret_cast<float4*>(&g_h1[node * FMID + c0 + 4]) =
            make_float4(acc[i][4], acc[i][5], acc[i][6], acc[i][7]);
    }
}

// CSR gather aggregation, 8 threads/node (thread = 4 cols of the 32-wide row).
// which=0: src=h1, epilogue r = relu(agg + self + b1)   -> g_r
// which=1: src=r,  epilogue a2 = agg + self             -> g_a2
__global__ void __launch_bounds__(256) k_gather(int which,
                                                const float* __restrict__ b1,
                                                int n) {
    int t = blockIdx.x * blockDim.x + threadIdx.x;
    int node = t >> 3;
    if (node >= n) return;
    int q = (t & 7) * 4;
    const float* __restrict__ src = which ? g_r : g_h1;

    int off = g_off[node];
    int end = off + g_cnt[node];
    float4 acc = make_float4(0.f, 0.f, 0.f, 0.f);
    for (int p = off; p < end; p++) {
        int2  rec = g_elist[p];                 // 8 lanes broadcast
        float nm  = __int_as_float(rec.y);
        float4 v = *reinterpret_cast<const float4*>(&src[rec.x + q]);
        acc.x += v.x * nm; acc.y += v.y * nm;
        acc.z += v.z * nm; acc.w += v.w * nm;
    }
    float w = 1.0f / g_deg[node];               // dinv^2 (self-loop norm)
    float4 sv = *reinterpret_cast<const float4*>(&src[node * FMID + q]);
    acc.x += w * sv.x; acc.y += w * sv.y;
    acc.z += w * sv.z; acc.w += w * sv.w;

    if (which == 0) {
        float4 bb = *reinterpret_cast<const float4*>(&b1[q]);
        *reinterpret_cast<float4*>(&g_r[node * FMID + q]) =
            make_float4(fmaxf(acc.x + bb.x, 0.f), fmaxf(acc.y + bb.y, 0.f),
                        fmaxf(acc.z + bb.z, 0.f), fmaxf(acc.w + bb.w, 0.f));
    } else {
        *reinterpret_cast<float4*>(&g_a2[node * FMID + q]) = acc;
    }
}

// GEMM2: out = a2@W2 + b2. Block = 256 thr, 128 nodes (25 KB smem).
__global__ void __launch_bounds__(256) k_gemm2(const float* __restrict__ W2,
                                               const float* __restrict__ b2,
                                               float* __restrict__ out, int n) {
    __shared__ float as_[32 * 132];  // a2 transposed [k][node], pad 4
    __shared__ float ws[32 * 64];
    int tid  = threadIdx.x;
    int base = blockIdx.x * 128;

    for (int i = tid; i < 32 * 64; i += 256) ws[i] = W2[i];
    for (int i = tid; i < 128 * 32; i += 256) {
        int node = i >> 5, k = i & 31;
        as_[k * 132 + node] =
            (base + node < n) ? g_a2[(base + node) * FMID + k] : 0.0f;
    }
    __syncthreads();

    int warp = tid >> 5, lane = tid & 31;
    int n0 = warp * 16 + (lane >> 3) * 4;
    int c0 = (lane & 7) * 8;

    float acc[4][8];
#pragma unroll
    for (int i = 0; i < 4; i++)
#pragma unroll
        for (int j = 0; j < 8; j++) acc[i][j] = 0.0f;

#pragma unroll 8
    for (int k = 0; k < 32; k++) {
        float4 xv = *reinterpret_cast<const float4*>(&as_[k * 132 + n0]);
        float4 wa = *reinterpret_cast<const float4*>(&ws[k * 64 + c0]);
        float4 wb = *reinterpret_cast<const float4*>(&ws[k * 64 + c0 + 4]);
        float xr[4] = {xv.x, xv.y, xv.z, xv.w};
        float wr[8] = {wa.x, wa.y, wa.z, wa.w, wb.x, wb.y, wb.z, wb.w};
#pragma unroll
        for (int i = 0; i < 4; i++)
#pragma unroll
            for (int j = 0; j < 8; j++) acc[i][j] += xr[i] * wr[j];
    }

    float4 ba  = *reinterpret_cast<const float4*>(&b2[c0]);
    float4 bbv = *reinterpret_cast<const float4*>(&b2[c0 + 4]);
#pragma unroll
    for (int i = 0; i < 4; i++) {
        int node = base + n0 + i;
        if (node >= n) break;
        *reinterpret_cast<float4*>(&out[node * FIN + c0]) =
            make_float4(acc[i][0] + ba.x, acc[i][1] + ba.y,
                        acc[i][2] + ba.z, acc[i][3] + ba.w);
        *reinterpret_cast<float4*>(&out[node * FIN + c0 + 4]) =
            make_float4(acc[i][4] + bbv.x, acc[i][5] + bbv.y,
                        acc[i][6] + bbv.z, acc[i][7] + bbv.w);
    }
}

// ---------------------------------------------------------------------------
extern "C" void kernel_launch(void* const* d_in, const int* in_sizes, int n_in,
                              void* d_out, int out_size) {
    const float* x  = (const float*)d_in[0];
    const void*  ei = d_in[1];                 // edge_index [2,E], int32
    const float* W1 = (const float*)d_in[2];
    const float* b1 = (const float*)d_in[3];
    const float* W2 = (const float*)d_in[4];
    const float* b2 = (const float*)d_in[5];
    float*       out = (float*)d_out;

    const int N = in_sizes[0] / FIN;   // 100000
    const int E = in_sizes[1] / 2;     // 1200000
    const int NB = (N + SCAN_B - 1) / SCAN_B;   // 98 scan blocks

    const int T = 256;
    k_count0   <<<(N + T - 1) / T, T>>>((const int*)ei, N);
    k_deg_count<<<(E + T - 1) / T, T>>>(ei, E);
    k_scan1    <<<NB, SCAN_B>>>(N);
    k_scan2    <<<1, 128>>>(NB);
    k_scan3    <<<(N + T - 1) / T, T>>>(N);
    k_fill     <<<(E + T - 1) / T, T>>>(ei, E);

    k_gemm1 <<<(N + 255) / 256, 256>>>(x, W1, N);
    k_gather<<<(N * 8 + T - 1) / T, T>>>(0, b1, N);
    k_gather<<<(N * 8 + T - 1) / T, T>>>(1, b1, N);
    k_gemm2 <<<(N + 127) / 128, 256>>>(W2, b2, out, N);
}